// round 5
// baseline (speedup 1.0000x reference)
#include <cuda_runtime.h>

#define BATCH 64
#define SEQ   1024
#define DMODEL 128
#define S134  134   // padded smem stride for 128-wide fp32 tiles (8-row step -> 16 banks apart)
#define SP66  66    // padded smem stride for 64-wide tiles

typedef unsigned long long u64;

// Scratch for projected q,k,v (allocation-free: __device__ globals)
__device__ float g_q[BATCH*SEQ*DMODEL];
__device__ float g_k[BATCH*SEQ*DMODEL];
__device__ float g_v[BATCH*SEQ*DMODEL];

// ---------- packed f32x2 helpers (SASS FFMA2: 2x fp32 FMA throughput) ----------
__device__ __forceinline__ void ffma2(u64 &d, u64 a, u64 b) {
    asm("fma.rn.f32x2 %0, %1, %2, %0;" : "+l"(d) : "l"(a), "l"(b));
}
__device__ __forceinline__ u64 pack2(float x, float y) {
    u64 r; asm("mov.b64 %0, {%1, %2};" : "=l"(r) : "f"(x), "f"(y)); return r;
}
__device__ __forceinline__ void unpack2(u64 v, float &x, float &y) {
    asm("mov.b64 {%0, %1}, %2;" : "=f"(x), "=f"(y) : "l"(v));
}
__device__ __forceinline__ u64 lds_pair(const float* p) {
    return *reinterpret_cast<const u64*>(p);
}
// deterministic fast tanh, ~1e-7 rel err
__device__ __forceinline__ float tanh_fast(float x) {
    float ax = fminf(fabsf(x), 20.0f);
    float e  = __expf(2.0f * ax);
    float t  = __fdividef(e - 1.0f, e + 1.0f);
    return copysignf(t, x);
}

// cooperative load 64x128 fp32 tile into smem (stride S134), 128 threads
__device__ __forceinline__ void load64x128(const float* __restrict__ g, int gstride,
                                           float* s, int tid) {
    #pragma unroll
    for (int it = 0; it < 16; ++it) {
        int f4 = tid + it * 128;
        int row = f4 >> 5, c4 = (f4 & 31) << 2;
        float4 v = *reinterpret_cast<const float4*>(g + (long)row * gstride + c4);
        float2* d = reinterpret_cast<float2*>(&s[row * S134 + c4]);
        d[0] = make_float2(v.x, v.y);
        d[1] = make_float2(v.z, v.w);
    }
}

// =====================================================================
// Projection: out[r][h] = tanh( sum_d x[r][d]*W[h][d] + b[h] ), 64x128 tile/CTA
// =====================================================================
__global__ void __launch_bounds__(128, 2)
proj_kernel(const float* __restrict__ x, const float* __restrict__ W,
            const float* __restrict__ bias, int sel)
{
    extern __shared__ float sm[];
    float* x_s = sm;                   // 64 * 134
    float* w_s = sm + 64 * S134;       // 128 * 134
    int tid = threadIdx.x;
    int r0 = blockIdx.x * 64;

    load64x128(x + (long)r0 * DMODEL, DMODEL, x_s, tid);
    #pragma unroll
    for (int it = 0; it < 32; ++it) {          // W: 128 x 128
        int f4 = tid + it * 128;
        int row = f4 >> 5, c4 = (f4 & 31) << 2;
        float4 v = *reinterpret_cast<const float4*>(W + (long)row * DMODEL + c4);
        float2* d = reinterpret_cast<float2*>(&w_s[row * S134 + c4]);
        d[0] = make_float2(v.x, v.y);
        d[1] = make_float2(v.z, v.w);
    }
    __syncthreads();

    int ty = tid >> 4, tx = tid & 15;          // 8 row-groups x 16 col-groups

    u64 acc[8][8] = {};
    #pragma unroll 4
    for (int dp = 0; dp < 64; ++dp) {          // d pairs
        u64 a[8], w[8];
        #pragma unroll
        for (int i = 0; i < 8; ++i) a[i] = lds_pair(&x_s[(ty*8 + i) * S134 + 2*dp]);
        #pragma unroll
        for (int j = 0; j < 8; ++j) w[j] = lds_pair(&w_s[(tx + j*16) * S134 + 2*dp]);
        #pragma unroll
        for (int i = 0; i < 8; ++i)
            #pragma unroll
            for (int j = 0; j < 8; ++j)
                ffma2(acc[i][j], a[i], w[j]);
    }

    float* outp = (sel == 0) ? g_q : (sel == 1) ? g_k : g_v;
    #pragma unroll
    for (int j = 0; j < 8; ++j) {
        int h = tx + j * 16;
        float bh = __ldg(&bias[h]);
        #pragma unroll
        for (int i = 0; i < 8; ++i) {
            int row = r0 + ty * 8 + i;
            float lo, hi; unpack2(acc[i][j], lo, hi);
            outp[(long)row * DMODEL + h] = tanh_fast(lo + hi + bh);
        }
    }
}

// =====================================================================
// Attention: per (batch, 64-query tile), stream 64-key blocks.
//   S = q k^T (FFMA2 pairs along d); p = mask ? exp(S) : 0 (no max-sub:
//   scores bounded << 88, masked lanes exact 0 -> identical to stable
//   softmax); O += p V (FFMA2 pairs along output h -> V needs no
//   transpose). Final O /= rowsum.
// =====================================================================
__global__ void __launch_bounds__(128, 2)
attn_kernel(const int* __restrict__ mask, float* __restrict__ out)
{
    extern __shared__ float sm[];
    float* q_s  = sm;                    // 64*134
    float* kv_s = q_s  + 64 * S134;      // 64*134 (k, then reused for v)
    float* p_s  = kv_s + 64 * S134;      // 64*66
    float* m_sf = p_s  + 64 * SP66;      // 64*66 (ints)
    float* red  = m_sf + 64 * SP66;      // 64*17
    float* rsum = red  + 64 * 17;        // 64
    int*   m_s  = (int*)m_sf;

    int tid = threadIdx.x;
    int b   = blockIdx.y;
    int q0  = blockIdx.x * 64;
    int ty  = tid >> 4, tx = tid & 15;

    load64x128(g_q + ((long)b * SEQ + q0) * DMODEL, DMODEL, q_s, tid);

    u64   oacc[8][4] = {};
    float rs[8] = {0,0,0,0,0,0,0,0};

    for (int jb = 0; jb < 16; ++jb) {
        int j0 = jb * 64;
        __syncthreads();   // prev GEMM2 done reading kv_s/p_s (iter 0: q_s visible)

        // load k tile
        load64x128(g_k + ((long)b * SEQ + j0) * DMODEL, DMODEL, kv_s, tid);
        // load mask tile: 64 rows x 64 ints (FIX: 64-wide addressing, 8 iters)
        {
            const int* mg = mask + ((long)b * SEQ + q0) * SEQ + j0;
            #pragma unroll
            for (int it = 0; it < 8; ++it) {
                int f4 = tid + it * 128;        // [0, 1024): 64 rows x 16 quad-groups
                int row = f4 >> 4, c4 = (f4 & 15) << 2;
                int4 v = *reinterpret_cast<const int4*>(mg + (long)row * SEQ + c4);
                int* d = &m_s[row * SP66 + c4];
                d[0] = v.x; d[1] = v.y; d[2] = v.z; d[3] = v.w;
            }
        }
        __syncthreads();

        // ---- GEMM1: S(64x64) = q(64x128) . k(64x128)^T ----
        u64 sacc[8][4] = {};
        #pragma unroll 4
        for (int dp = 0; dp < 64; ++dp) {
            u64 a[8], kk[4];
            #pragma unroll
            for (int i = 0; i < 8; ++i) a[i]  = lds_pair(&q_s [(ty*8 + i ) * S134 + 2*dp]);
            #pragma unroll
            for (int j = 0; j < 4; ++j) kk[j] = lds_pair(&kv_s[(tx + j*16) * S134 + 2*dp]);
            #pragma unroll
            for (int i = 0; i < 8; ++i)
                #pragma unroll
                for (int j = 0; j < 4; ++j)
                    ffma2(sacc[i][j], a[i], kk[j]);
        }
        // mask + exp + stage P, accumulate row partial sums
        #pragma unroll
        for (int i = 0; i < 8; ++i) {
            int row = ty * 8 + i;
            #pragma unroll
            for (int j = 0; j < 4; ++j) {
                int col = tx + j * 16;
                float lo, hi; unpack2(sacc[i][j], lo, hi);
                float s = lo + hi;
                float p = (m_s[row * SP66 + col] != 0) ? __expf(s) : 0.0f;
                rs[i] += p;
                p_s[row * SP66 + col] = p;
            }
        }
        __syncthreads();   // GEMM1 done with kv_s; p_s complete

        // load v tile into kv_s
        load64x128(g_v + ((long)b * SEQ + j0) * DMODEL, DMODEL, kv_s, tid);
        __syncthreads();

        // ---- GEMM2: O(64x128) += P(64x64) . V(64x128) ----
        #pragma unroll 2
        for (int jp = 0; jp < 32; ++jp) {
            u64 pd0[8], pd1[8];
            #pragma unroll
            for (int i = 0; i < 8; ++i) {
                float2 pp = *reinterpret_cast<const float2*>(&p_s[(ty*8 + i) * SP66 + 2*jp]);
                pd0[i] = pack2(pp.x, pp.x);
                pd1[i] = pack2(pp.y, pp.y);
            }
            u64 v0[4], v1[4];
            #pragma unroll
            for (int j = 0; j < 4; ++j) {
                int hp2 = 2 * (tx + j * 16);
                v0[j] = lds_pair(&kv_s[(2*jp    ) * S134 + hp2]);
                v1[j] = lds_pair(&kv_s[(2*jp + 1) * S134 + hp2]);
            }
            #pragma unroll
            for (int i = 0; i < 8; ++i)
                #pragma unroll
                for (int j = 0; j < 4; ++j) {
                    ffma2(oacc[i][j], pd0[i], v0[j]);
                    ffma2(oacc[i][j], pd1[i], v1[j]);
                }
        }
    }

    // rowsum reduction across the 16 col-thread partials
    __syncthreads();
    #pragma unroll
    for (int i = 0; i < 8; ++i) red[(ty*8 + i) * 17 + tx] = rs[i];
    __syncthreads();
    if (tid < 64) {
        float s = 0.0f;
        #pragma unroll
        for (int t = 0; t < 16; ++t) s += red[tid * 17 + t];
        rsum[tid] = s;
    }
    __syncthreads();

    #pragma unroll
    for (int i = 0; i < 8; ++i) {
        int row = ty * 8 + i;
        float inv = __fdividef(1.0f, rsum[row]);
        #pragma unroll
        for (int j = 0; j < 4; ++j) {
            float lo, hi; unpack2(oacc[i][j], lo, hi);
            float2 o = make_float2(lo * inv, hi * inv);
            *reinterpret_cast<float2*>(
                &out[((long)b * SEQ + q0 + row) * DMODEL + 2 * (tx + j * 16)]) = o;
        }
    }
}

// =====================================================================
extern "C" void kernel_launch(void* const* d_in, const int* in_sizes, int n_in,
                              void* d_out, int out_size)
{
    const float* x    = (const float*)d_in[0];
    const int*   mask = (const int*)  d_in[1];
    const float* Wv   = (const float*)d_in[2];
    const float* bv   = (const float*)d_in[3];
    const float* Wk   = (const float*)d_in[4];
    const float* bk   = (const float*)d_in[5];
    const float* Wq   = (const float*)d_in[6];
    const float* bq   = (const float*)d_in[7];
    float* out = (float*)d_out;

    int smem_proj = (64 * S134 + 128 * S134) * (int)sizeof(float);                 // ~100.5 KB
    int smem_attn = (64*S134 + 64*S134 + 64*SP66 + 64*SP66 + 64*17 + 64)
                    * (int)sizeof(float);                                          // ~104.5 KB
    cudaFuncSetAttribute(proj_kernel, cudaFuncAttributeMaxDynamicSharedMemorySize, smem_proj);
    cudaFuncSetAttribute(attn_kernel, cudaFuncAttributeMaxDynamicSharedMemorySize, smem_attn);

    // 65536 rows / 64 per CTA = 1024 CTAs per projection
    proj_kernel<<<1024, 128, smem_proj>>>(x, Wq, bq, 0);
    proj_kernel<<<1024, 128, smem_proj>>>(x, Wk, bk, 1);
    proj_kernel<<<1024, 128, smem_proj>>>(x, Wv, bv, 2);

    attn_kernel<<<dim3(16, BATCH), 128, smem_attn>>>(mask, out);
}